// round 16
// baseline (speedup 1.0000x reference)
#include <cuda_runtime.h>
#include <cuda_fp16.h>

// FeaturesLinear: out[b,:] = sum_t user_W[fid]*rating_W[rx] + item_W[item_ids[b]] + bias
// K1: fp32 -> fp16 mirror of user_W (static scratch, 25.6 MB).
// K2: ONE segment per warp, fixed unrolled loop, PAIRWISE-WIDENED:
//     each iteration handles two time steps — lanes 0-15 LDG.128 the full
//     256B row of step 2p, lanes 16-31 of step 2p+1; one shfl (src=2p+half)
//     broadcasts each half its packed fid|rx; one LDS.128 rating fetch.
//     MIO issues per 2 steps: 3 (was 6). Each lane accumulates 8 dims for its
//     parity; cross-parity combine via 8 shfl.xor(16) at the end.

#define HIST 50
#define THREADS 128
#define NU 100001          // NUM_ITEMS + 1
#define NU16 (NU * 16)     // uint4 count of the fp16 mirror
#define FULL 0xffffffffu

// fp16 mirror of user_W: NU rows x 128 halves = 25.6 MB. Row = 256 bytes.
__device__ __align__(16) uint2 g_uW_h[NU * 32];

__global__ __launch_bounds__(256)
void convert_userW_kernel(const float4* __restrict__ userW)
{
    uint4* __restrict__ dst = reinterpret_cast<uint4*>(g_uW_h);
    const int stride = gridDim.x * blockDim.x;
    for (int i = blockIdx.x * blockDim.x + threadIdx.x; i < NU16; i += stride) {
        const float4 v0 = __ldcs(&userW[2 * i]);
        const float4 v1 = __ldcs(&userW[2 * i + 1]);
        const __half2 a = __floats2half2_rn(v0.x, v0.y);
        const __half2 b = __floats2half2_rn(v0.z, v0.w);
        const __half2 c = __floats2half2_rn(v1.x, v1.y);
        const __half2 d = __floats2half2_rn(v1.z, v1.w);
        uint4 o;
        o.x = *reinterpret_cast<const unsigned*>(&a);
        o.y = *reinterpret_cast<const unsigned*>(&b);
        o.z = *reinterpret_cast<const unsigned*>(&c);
        o.w = *reinterpret_cast<const unsigned*>(&d);
        dst[i] = o;
    }
}

__device__ __forceinline__ __half2 u2h(unsigned v) {
    return *reinterpret_cast<const __half2*>(&v);
}

__global__ __launch_bounds__(THREADS, 9)
void features_linear_kernel(const int*    __restrict__ fids,      // [T]
                            const float*  __restrict__ ratings,   // [T]
                            const int*    __restrict__ segs,      // [T]
                            const int*    __restrict__ item_ids,  // [B]
                            const float4* __restrict__ ratingW,   // [10, 32]
                            const float4* __restrict__ itemW,     // [Ni, 32]
                            const float4* __restrict__ bias,      // [32]
                            float4*       __restrict__ out,       // [B, 32]
                            int batch)
{
    // fp16 rating table: row rx = 16 x uint4 (8 halves per 16B chunk), 2.5 KB.
    __shared__ uint4  s_rw[10 * 16];
    __shared__ float4 s_bias[32];

    for (int j = threadIdx.x; j < 10 * 16; j += THREADS) {
        const float4 f0 = ratingW[2 * j];
        const float4 f1 = ratingW[2 * j + 1];
        const __half2 a = __floats2half2_rn(f0.x, f0.y);
        const __half2 b = __floats2half2_rn(f0.z, f0.w);
        const __half2 c = __floats2half2_rn(f1.x, f1.y);
        const __half2 d = __floats2half2_rn(f1.z, f1.w);
        uint4 w;
        w.x = *reinterpret_cast<const unsigned*>(&a);
        w.y = *reinterpret_cast<const unsigned*>(&b);
        w.z = *reinterpret_cast<const unsigned*>(&c);
        w.w = *reinterpret_cast<const unsigned*>(&d);
        s_rw[j] = w;
    }
    if (threadIdx.x < 32) s_bias[threadIdx.x] = bias[threadIdx.x];
    __syncthreads();

    const int gwarp = (blockIdx.x * THREADS + threadIdx.x) >> 5;
    const int lane  = threadIdx.x & 31;
    if (gwarp >= batch) return;

    const int half = lane >> 4;           // parity of time step this lane serves
    const int hl   = lane & 15;           // 16B chunk within the 256B row

    const int base = gwarp * HIST;

    // ---- Prefetch 50 (fid, rx) pairs packed into 2 regs/lane ----
    int c0, c1 = 0;
    {
        const int f = __ldg(&fids[base + lane]);
        const float r = __ldg(&ratings[base + lane]);
        const int rx = min(max(__float2int_rn((r - 0.5f) * 2.0f), 0), 9);
        c0 = f | (rx << 20);
    }
    if (lane < HIST - 32) {
        const int f = __ldg(&fids[base + 32 + lane]);
        const float r = __ldg(&ratings[base + 32 + lane]);
        const int rx = min(max(__float2int_rn((r - 0.5f) * 2.0f), 0), 9);
        c1 = f | (rx << 20);
    }

    // ---- Epilogue loads hoisted (8-dim-per-lane layout) ----
    const int row = __ldg(&segs[base]);
    const int iid = __ldg(&item_ids[row]);
    const float4 it0 = __ldg(&itemW[(size_t)iid * 32 + 2 * hl]);
    const float4 it1 = __ldg(&itemW[(size_t)iid * 32 + 2 * hl + 1]);

    const char* __restrict__ uWb = reinterpret_cast<const char*>(g_uW_h);
    const unsigned chunkoff = (unsigned)hl << 4;    // 16B per lane within row

    float accf[8];
    #pragma unroll
    for (int j = 0; j < 8; j++) accf[j] = 0.0f;
    const __half2 hz = __floats2half2_rn(0.0f, 0.0f);
    __half2 ah0 = hz, ah1 = hz, ah2 = hz, ah3 = hz;

    // ---- Main loop: 25 pair-iterations, fully unrolled.
    // One LDG.128 + one LDS.128 + one SHFL serve TWO time steps. ----
    #pragma unroll
    for (int p = 0; p < HIST / 2; p++) {
        const int src = 2 * p + half;     // per-lane shfl source: own parity step
        const int packed = (p < 16) ? __shfl_sync(FULL, c0, src)
                                    : __shfl_sync(FULL, c1, src - 32);
        const int fid = packed & 0xFFFFF;
        const int rx  = packed >> 20;

        const unsigned off = ((unsigned)fid << 8) | chunkoff;
        const uint4 u = __ldg(reinterpret_cast<const uint4*>(uWb + off)); // LDG.128
        const uint4 w = s_rw[(rx << 4) + hl];                             // LDS.128

        ah0 = __hfma2(u2h(u.x), u2h(w.x), ah0);
        ah1 = __hfma2(u2h(u.y), u2h(w.y), ah1);
        ah2 = __hfma2(u2h(u.z), u2h(w.z), ah2);
        ah3 = __hfma2(u2h(u.w), u2h(w.w), ah3);

        if ((p & 3) == 3 || p == HIST / 2 - 1) {   // compile-time flush to fp32
            float2 f;
            f = __half22float2(ah0); accf[0] += f.x; accf[1] += f.y;
            f = __half22float2(ah1); accf[2] += f.x; accf[3] += f.y;
            f = __half22float2(ah2); accf[4] += f.x; accf[5] += f.y;
            f = __half22float2(ah3); accf[6] += f.x; accf[7] += f.y;
            ah0 = hz; ah1 = hz; ah2 = hz; ah3 = hz;
        }
    }

    // ---- Cross-parity combine: lanes l and l+16 hold complementary partial
    // sums of the same 8 dims. ----
    #pragma unroll
    for (int j = 0; j < 8; j++)
        accf[j] += __shfl_xor_sync(FULL, accf[j], 16);

    if (half == 0) {
        const float4 b0 = s_bias[2 * hl];
        const float4 b1 = s_bias[2 * hl + 1];
        float4 o0, o1;
        o0.x = accf[0] + it0.x + b0.x;
        o0.y = accf[1] + it0.y + b0.y;
        o0.z = accf[2] + it0.z + b0.z;
        o0.w = accf[3] + it0.w + b0.w;
        o1.x = accf[4] + it1.x + b1.x;
        o1.y = accf[5] + it1.y + b1.y;
        o1.z = accf[6] + it1.z + b1.z;
        o1.w = accf[7] + it1.w + b1.w;
        out[(size_t)row * 32 + 2 * hl]     = o0;
        out[(size_t)row * 32 + 2 * hl + 1] = o1;
    }
}

extern "C" void kernel_launch(void* const* d_in, const int* in_sizes, int n_in,
                              void* d_out, int out_size)
{
    const int*    fids     = (const int*)   d_in[0];
    const float*  ratings  = (const float*) d_in[1];
    const int*    segs     = (const int*)   d_in[2];
    const int*    item_ids = (const int*)   d_in[3];
    const float4* userW    = (const float4*)d_in[4];
    const float4* ratingW  = (const float4*)d_in[5];
    const float4* itemW    = (const float4*)d_in[6];
    const float4* bias     = (const float4*)d_in[7];
    float4*       out      = (float4*)      d_out;

    const int batch  = in_sizes[3];                 // item_ids count
    const int blocks = (batch * 32 + THREADS - 1) / THREADS;   // 1 warp/segment

    convert_userW_kernel<<<2048, 256>>>(userW);
    features_linear_kernel<<<blocks, THREADS>>>(
        fids, ratings, segs, item_ids, ratingW, itemW, bias, out, batch);
}